// round 15
// baseline (speedup 1.0000x reference)
#include <cuda_runtime.h>
#include <math.h>

// Problem constants
#define NB   8
#define T1   512
#define T2   128
#define EE   64      // E
#define G3   192     // 3*E
#define DLN  256
#define CTXD 128     // 2*E
#define VOC  129     // LA+1
#define NS   126     // T2-2 valid conv output positions
#define SLAB 128     // padded slab rows (power of 2)

// Scratch (device globals)
__device__ float g_tab[2 * VOC * G3];        // per-dir input-gate table
__device__ float g_ctx[NB * T2 * CTXD];      // [b][s][fwd|bwd]
__device__ float g_Q00[NB * T2 * EE];
__device__ float g_Qm [NB * T2 * EE];
__device__ float g_Q11[NB * T2 * EE];
__device__ float g_cs[NB * T2];              // ctx . w_c
__device__ float g_bias2[EE];

__device__ __forceinline__ float tanhapx(float v) {
    float r;
    asm("tanh.approx.f32 %0, %1;" : "=f"(r) : "f"(v));
    return r;
}
__device__ __forceinline__ float sigapx(float v) {
    return fmaf(0.5f, tanhapx(0.5f * v), 0.5f);
}
__device__ __forceinline__ unsigned long long packf2(float lo, float hi) {
    unsigned long long r;
    asm("mov.b64 %0, {%1, %2};" : "=l"(r) : "f"(lo), "f"(hi));
    return r;
}
__device__ __forceinline__ void fma2(unsigned long long& acc,
                                     unsigned long long a, unsigned long long b) {
    asm("fma.rn.f32x2 %0, %1, %2, %0;" : "+l"(acc) : "l"(a), "l"(b));
}
__device__ __forceinline__ float unpack_sum(unsigned long long v) {
    float lo, hi;
    asm("mov.b64 {%0, %1}, %2;" : "=f"(lo), "=f"(hi) : "l"(v));
    return lo + hi;
}

// ---------------------------------------------------------------------------
// Kernel T: input-gate table  tab[dir][c][u] = emb[c]@K_dir + b0[u]
// grid (129,2), block 192
// ---------------------------------------------------------------------------
__global__ void k_tab(const float* __restrict__ emb_table,
                      const float* __restrict__ Kf, const float* __restrict__ bf,
                      const float* __restrict__ Kb, const float* __restrict__ bb) {
    int c = blockIdx.x, dir = blockIdx.y;
    int u = threadIdx.x;
    __shared__ float e_sm[EE];
    if (u < EE) e_sm[u] = emb_table[c * EE + u];
    __syncthreads();
    const float* K = dir ? Kb : Kf;
    float a0 = (dir ? bb : bf)[u], a1 = 0.f, a2 = 0.f, a3 = 0.f;
    const float4* e4 = (const float4*)e_sm;
#pragma unroll
    for (int k = 0; k < 16; k++) {
        float4 hv = e4[k];
        int e = 4 * k;
        a0 = fmaf(hv.x, K[(e + 0) * G3 + u], a0);
        a1 = fmaf(hv.y, K[(e + 1) * G3 + u], a1);
        a2 = fmaf(hv.z, K[(e + 2) * G3 + u], a2);
        a3 = fmaf(hv.w, K[(e + 3) * G3 + u], a3);
    }
    g_tab[(dir * VOC + c) * G3 + u] = (a0 + a1) + (a2 + a3);
}

// ---------------------------------------------------------------------------
// Kernel G: GRU (R11 configuration). grid (8,2), block 256
// (64 units x 4 e-quarters). One barrier/step (ping-pong h).
// f32x2 packed FMA, tanh.approx, x staged in smem.
// ---------------------------------------------------------------------------
__global__ void __launch_bounds__(256) k_gru(const int* __restrict__ char_seq,
                      const float* __restrict__ Rf, const float* __restrict__ bf,
                      const float* __restrict__ Rb, const float* __restrict__ bb) {
    extern __shared__ float x_sm[];              // [128][192]
    __shared__ float hbuf[2][EE];
    __shared__ int   s_char[T2];
    int b = blockIdx.x, dir = blockIdx.y;
    int tid = threadIdx.x;
    int i = tid >> 2, q = tid & 3;               // unit, e-quarter

    const float* R    = dir ? Rb : Rf;
    const float* bias = dir ? bb : bf;

    unsigned long long Rz2[8], Rr2[8], Rh2[8];
#pragma unroll
    for (int k = 0; k < 8; k++) {
        int e = 16 * q + 2 * k;
        Rz2[k] = packf2(R[e * G3 + i],        R[(e + 1) * G3 + i]);
        Rr2[k] = packf2(R[e * G3 + 64 + i],   R[(e + 1) * G3 + 64 + i]);
        Rh2[k] = packf2(R[e * G3 + 128 + i],  R[(e + 1) * G3 + 128 + i]);
    }
    float bz = (q == 0) ? bias[G3 + i]        : 0.0f;
    float br = (q == 0) ? bias[G3 + 64 + i]   : 0.0f;
    float bh = (q == 0) ? bias[G3 + 128 + i]  : 0.0f;

    if (tid < T2) s_char[tid] = char_seq[b * T2 + tid];
    if (tid < EE) hbuf[0][tid] = 0.0f;
    __syncthreads();

    const float* tab = g_tab + dir * VOC * G3;
    for (int idx = tid; idx < T2 * G3; idx += 256) {
        int row = idx / G3, cc = idx - row * G3;
        x_sm[idx] = tab[s_char[row] * G3 + cc];
    }
    __syncthreads();

    float h = 0.0f, y = 0.0f;
    int p = 0;
    for (int t = 0; t < T2; t++) {
        int tt = dir ? (T2 - 1 - t) : t;
        float xz = x_sm[tt * G3 + i];
        float xr = x_sm[tt * G3 + 64 + i];
        float xh = x_sm[tt * G3 + 128 + i];

        const unsigned long long* h2 =
            (const unsigned long long*)(hbuf[p] + 16 * q);
        unsigned long long az2 = packf2(bz, 0.0f);
        unsigned long long ar2 = packf2(br, 0.0f);
        unsigned long long ah2 = packf2(bh, 0.0f);
#pragma unroll
        for (int k = 0; k < 8; k++) {
            unsigned long long hv = h2[k];
            fma2(az2, hv, Rz2[k]);
            fma2(ar2, hv, Rr2[k]);
            fma2(ah2, hv, Rh2[k]);
        }
        float az = unpack_sum(az2);
        float ar = unpack_sum(ar2);
        float ah = unpack_sum(ah2);
        az += __shfl_xor_sync(0xffffffffu, az, 1);
        ar += __shfl_xor_sync(0xffffffffu, ar, 1);
        ah += __shfl_xor_sync(0xffffffffu, ah, 1);
        az += __shfl_xor_sync(0xffffffffu, az, 2);
        ar += __shfl_xor_sync(0xffffffffu, ar, 2);
        ah += __shfl_xor_sync(0xffffffffu, ah, 2);

        float z  = sigapx(xz + az);
        float r  = sigapx(xr + ar);
        float hh = tanhapx(fmaf(r, ah, xh));
        float hn = fmaf(z, h - hh, hh);          // z*h + (1-z)*hh
        if (s_char[tt] != 0) { h = hn; y = hn; }
        if (q == 0) {
            hbuf[1 - p][i] = h;
            g_ctx[(b * T2 + tt) * CTXD + dir * EE + i] = y;
        }
        p ^= 1;
        __syncthreads();
    }
}

// ---------------------------------------------------------------------------
// Kernel PQ v2: s-tiled, weight-stationary. grid (8 b, 16), block 256
// (64 o x 4 s-groups; each s-group handles 2 of the block's 8 s values).
// Each weight element is fetched once per block and reused for 2 s.
// ---------------------------------------------------------------------------
__global__ void __launch_bounds__(256) k_pq(const float* __restrict__ conv1_w,
                     const float* __restrict__ conv2_w,
                     const float* __restrict__ conv1_b,
                     const float* __restrict__ conv2_b,
                     const float* __restrict__ w_char) {
    __shared__ float ctx_sm[8][CTXD];            // 4 KB
    __shared__ float p_sm[8][2][EE];             // 4 KB
    int b = blockIdx.x, s0 = blockIdx.y * 8;
    int tid = threadIdx.x;
    int o = tid & 63, sg = tid >> 6;
    int sa = 2 * sg, sb = sa + 1;                // local s indices

    // Load ctx rows for the 8 s values (coalesced).
    const float* ctxg = g_ctx + (b * T2 + s0) * CTXD;
#pragma unroll
    for (int it = 0; it < 4; it++) {
        int idx = tid + it * 256;                // 8*128 = 1024
        ctx_sm[idx >> 7][idx & 127] = ctxg[idx];
    }
    __syncthreads();

    // cs: warp w reduces ctx[s0+w] . w_c   (8 warps = 8 s)
    {
        int w = tid >> 5, lane = tid & 31;
        float v = ctx_sm[w][lane]       * w_char[DLN + lane]
                + ctx_sm[w][lane + 32]  * w_char[DLN + lane + 32]
                + ctx_sm[w][lane + 64]  * w_char[DLN + lane + 64]
                + ctx_sm[w][lane + 96]  * w_char[DLN + lane + 96];
#pragma unroll
        for (int off = 16; off; off >>= 1)
            v += __shfl_xor_sync(0xffffffffu, v, off);
        if (lane == 0) g_cs[b * T2 + s0 + w] = v;
    }

    // P phase: P[tap][s][o] = sum_c ctx[s][c] * W1[tap][c][o]
    {
        const float* W0 = conv1_w;                   // tap0 [c][o]
        const float* W1 = conv1_w + CTXD * EE;       // tap1
        float p0a = 0.f, p1a = 0.f, p0b = 0.f, p1b = 0.f;
#pragma unroll 4
        for (int c = 0; c < CTXD; c++) {
            float w0 = W0[c * EE + o], w1 = W1[c * EE + o];
            float ca = ctx_sm[sa][c],  cb = ctx_sm[sb][c];
            p0a = fmaf(ca, w0, p0a);  p1a = fmaf(ca, w1, p1a);
            p0b = fmaf(cb, w0, p0b);  p1b = fmaf(cb, w1, p1b);
        }
        p_sm[sa][0][o] = p0a;  p_sm[sa][1][o] = p1a;
        p_sm[sb][0][o] = p0b;  p_sm[sb][1][o] = p1b;
    }
    __syncthreads();

    // Q phase: Q00 = P0@W20, Qm = P1@W20 + P0@W21, Q11 = P1@W21 (same s).
    {
        const float* W20 = conv2_w;
        const float* W21 = conv2_w + EE * EE;
        float q00a = 0.f, qxa = 0.f, qya = 0.f, q11a = 0.f;
        float q00b = 0.f, qxb = 0.f, qyb = 0.f, q11b = 0.f;
#pragma unroll 4
        for (int k = 0; k < EE; k++) {
            float w20 = W20[k * EE + o], w21 = W21[k * EE + o];
            float pa0 = p_sm[sa][0][k], pa1 = p_sm[sa][1][k];
            float pb0 = p_sm[sb][0][k], pb1 = p_sm[sb][1][k];
            q00a = fmaf(pa0, w20, q00a);  qxa  = fmaf(pa1, w20, qxa);
            qya  = fmaf(pa0, w21, qya);   q11a = fmaf(pa1, w21, q11a);
            q00b = fmaf(pb0, w20, q00b);  qxb  = fmaf(pb1, w20, qxb);
            qyb  = fmaf(pb0, w21, qyb);   q11b = fmaf(pb1, w21, q11b);
        }
        long ia = (long)(b * T2 + s0 + sa) * EE + o;
        long ib = (long)(b * T2 + s0 + sb) * EE + o;
        g_Q00[ia] = q00a;  g_Qm[ia] = qxa + qya;  g_Q11[ia] = q11a;
        g_Q00[ib] = q00b;  g_Qm[ib] = qxb + qyb;  g_Q11[ib] = q11b;
    }

    // bias2 (once)
    if (b == 0 && blockIdx.y == 0 && tid < EE) {
        const float* W20 = conv2_w;
        const float* W21 = conv2_w + EE * EE;
        float bb2 = conv2_b[tid];
#pragma unroll
        for (int k = 0; k < EE; k++)
            bb2 = fmaf(conv1_b[k], W20[k * EE + tid] + W21[k * EE + tid], bb2);
        g_bias2[tid] = bb2;
    }
}

// ---------------------------------------------------------------------------
// Kernel D: smem slope/base slab + 4-way t-register-blocked max-plus.
// grid (8 b, 16 tb), block 512 (8 t-groups x 64 o). 32 t per block.
// Dynamic smem: float2 sb[128*64] = 64 KB (padded: s>=126 -> {0,-INF}).
// ---------------------------------------------------------------------------
__global__ void __launch_bounds__(512) k_main(const float* __restrict__ lstm,
                                              const float* __restrict__ w_char,
                                              const float* __restrict__ b_char,
                                              float* __restrict__ out_final,
                                              float* __restrict__ out_cw) {
    extern __shared__ float2 sb_sm[];            // [128*64] {slope, base}
    __shared__ float A_sm[32];
    __shared__ float garr[T2];
    int b = blockIdx.x, t0 = blockIdx.y * 32;
    int tid = threadIdx.x;

    float wi = w_char[DLN + CTXD + 1];
    if (tid < T2) garr[tid] = g_cs[b * T2 + tid] + wi * (float)tid;

    {
        int grp = tid >> 4, l16 = tid & 15;
        const float4* row4 = (const float4*)(lstm + ((long)(b * T1 + t0 + grp)) * DLN);
        const float4* wl4  = (const float4*)w_char;
        float pv = 0.0f;
#pragma unroll
        for (int k = 0; k < 4; k++) {
            float4 rv = row4[l16 + 16 * k], wv = wl4[l16 + 16 * k];
            pv += rv.x * wv.x + rv.y * wv.y + rv.z * wv.z + rv.w * wv.w;
        }
#pragma unroll
        for (int off = 8; off; off >>= 1)
            pv += __shfl_xor_sync(0xffffffffu, pv, off);
        if (l16 == 0)
            A_sm[grp] = pv + w_char[DLN + CTXD] * (float)(t0 + grp) + b_char[0];
    }
    __syncthreads();

    {
        float* cwb = out_cw + ((long)(b * T1 + t0)) * T2;
#pragma unroll
        for (int it = 0; it < 8; it++) {
            int idx = tid + it * 512;
            int tl = idx >> 7, s = idx & (T2 - 1);
            cwb[tl * T2 + s] = A_sm[tl] + garr[s];
        }
    }

    {
        int ocol = tid & 63;
        float b2 = g_bias2[ocol];
        const float* Qb  = g_Q00 + b * T2 * EE;
        const float* Qmb = g_Qm  + b * T2 * EE;
        const float* Q1b = g_Q11 + b * T2 * EE;
#pragma unroll
        for (int it = 0; it < 16; it++) {
            int idx = tid + it * 512;
            int s = idx >> 6;
            float slope = 0.0f, base = -INFINITY;
            if (s < NS) {
                float q0 = Qb [idx];
                float qm = Qmb[idx + EE];
                float q1 = Q1b[idx + 2 * EE];
                slope = (q0 + qm) + q1;
                base  = fmaf(garr[s], q0,
                        fmaf(garr[s + 1], qm,
                        fmaf(garr[s + 2], q1, b2)));
            }
            sb_sm[idx] = make_float2(slope, base);
        }
    }
    __syncthreads();

    {
        int tg = tid >> 6, o = tid & 63;
        float A0 = A_sm[tg + 0],  A1 = A_sm[tg + 8];
        float A2 = A_sm[tg + 16], A3 = A_sm[tg + 24];
        float m0 = -INFINITY, m1 = -INFINITY, m2 = -INFINITY, m3 = -INFINITY;
        const float2* sb = sb_sm + o;
#pragma unroll 8
        for (int s = 0; s < SLAB; s++) {
            float2 v = sb[s * EE];
            m0 = fmaxf(m0, fmaf(A0, v.x, v.y));
            m1 = fmaxf(m1, fmaf(A1, v.x, v.y));
            m2 = fmaxf(m2, fmaf(A2, v.x, v.y));
            m3 = fmaxf(m3, fmaf(A3, v.x, v.y));
        }
        long ob = (long)(b * T1 + t0) * EE + o;
        out_final[ob + (tg + 0)  * EE] = m0;
        out_final[ob + (tg + 8)  * EE] = m1;
        out_final[ob + (tg + 16) * EE] = m2;
        out_final[ob + (tg + 24) * EE] = m3;
    }
}

// ---------------------------------------------------------------------------
extern "C" void kernel_launch(void* const* d_in, const int* in_sizes, int n_in,
                              void* d_out, int out_size) {
    const float* lstm     = (const float*)d_in[0];
    const int*   char_seq = (const int*)  d_in[1];
    const float* emb      = (const float*)d_in[2];
    const float* Kf       = (const float*)d_in[3];
    const float* Rf       = (const float*)d_in[4];
    const float* bf       = (const float*)d_in[5];
    const float* Kb       = (const float*)d_in[6];
    const float* Rb       = (const float*)d_in[7];
    const float* bb       = (const float*)d_in[8];
    const float* w_char   = (const float*)d_in[9];
    const float* b_char   = (const float*)d_in[10];
    const float* conv1_w  = (const float*)d_in[11];
    const float* conv1_b  = (const float*)d_in[12];
    const float* conv2_w  = (const float*)d_in[13];
    const float* conv2_b  = (const float*)d_in[14];

    float* out_final = (float*)d_out;                 // (8,512,64)
    float* out_cw    = out_final + NB * T1 * EE;      // (8,512,128,1)

    (void)cudaFuncSetAttribute(k_gru, cudaFuncAttributeMaxDynamicSharedMemorySize,
                               T2 * G3 * (int)sizeof(float));
    (void)cudaFuncSetAttribute(k_main, cudaFuncAttributeMaxDynamicSharedMemorySize,
                               SLAB * EE * (int)sizeof(float2));

    k_tab<<<dim3(VOC, 2), G3>>>(emb, Kf, bf, Kb, bb);
    k_gru<<<dim3(NB, 2), 256, T2 * G3 * sizeof(float)>>>(char_seq, Rf, bf, Rb, bb);
    k_pq<<<dim3(NB, 16), 256>>>(conv1_w, conv2_w, conv1_b, conv2_b, w_char);
    k_main<<<dim3(NB, 16), 512, SLAB * EE * sizeof(float2)>>>(lstm, w_char, b_char,
                                                              out_final, out_cw);
}

// round 16
// speedup vs baseline: 1.0542x; 1.0542x over previous
#include <cuda_runtime.h>
#include <math.h>

// Problem constants
#define NB   8
#define T1   512
#define T2   128
#define EE   64      // E
#define G3   192     // 3*E
#define DLN  256
#define CTXD 128     // 2*E
#define VOC  129     // LA+1
#define NS   126     // T2-2 valid conv output positions
#define SLAB 128     // padded slab rows (power of 2)

// Scratch (device globals)
__device__ float g_tab[2 * VOC * G3];        // per-dir input-gate table
__device__ float g_ctx[NB * T2 * CTXD];      // [b][s][fwd|bwd]
__device__ float g_Q00[NB * T2 * EE];
__device__ float g_Qm [NB * T2 * EE];
__device__ float g_Q11[NB * T2 * EE];
__device__ float g_cs[NB * T2];              // ctx . w_c
__device__ float g_a [NB * T1];              // A = lstm.w_l + w_t*t + bc
__device__ float g_bias2[EE];

__device__ __forceinline__ float tanhapx(float v) {
    float r;
    asm("tanh.approx.f32 %0, %1;" : "=f"(r) : "f"(v));
    return r;
}
__device__ __forceinline__ float sigapx(float v) {
    return fmaf(0.5f, tanhapx(0.5f * v), 0.5f);
}
__device__ __forceinline__ unsigned long long packf2(float lo, float hi) {
    unsigned long long r;
    asm("mov.b64 %0, {%1, %2};" : "=l"(r) : "f"(lo), "f"(hi));
    return r;
}
__device__ __forceinline__ void fma2(unsigned long long& acc,
                                     unsigned long long a, unsigned long long b) {
    asm("fma.rn.f32x2 %0, %1, %2, %0;" : "+l"(acc) : "l"(a), "l"(b));
}
__device__ __forceinline__ float unpack_sum(unsigned long long v) {
    float lo, hi;
    asm("mov.b64 {%0, %1}, %2;" : "=f"(lo), "=f"(hi) : "l"(v));
    return lo + hi;
}

// ---------------------------------------------------------------------------
// Kernel T: input-gate table for ONE direction. grid 129, block 192.
// ---------------------------------------------------------------------------
__global__ void k_tab(int dir,
                      const float* __restrict__ emb_table,
                      const float* __restrict__ K, const float* __restrict__ bias) {
    int c = blockIdx.x;
    int u = threadIdx.x;
    __shared__ float e_sm[EE];
    if (u < EE) e_sm[u] = emb_table[c * EE + u];
    __syncthreads();
    float a0 = bias[u], a1 = 0.f, a2 = 0.f, a3 = 0.f;
    const float4* e4 = (const float4*)e_sm;
#pragma unroll
    for (int k = 0; k < 16; k++) {
        float4 hv = e4[k];
        int e = 4 * k;
        a0 = fmaf(hv.x, K[(e + 0) * G3 + u], a0);
        a1 = fmaf(hv.y, K[(e + 1) * G3 + u], a1);
        a2 = fmaf(hv.z, K[(e + 2) * G3 + u], a2);
        a3 = fmaf(hv.w, K[(e + 3) * G3 + u], a3);
    }
    g_tab[(dir * VOC + c) * G3 + u] = (a0 + a1) + (a2 + a3);
}

// ---------------------------------------------------------------------------
// Kernel A: g_a[b,t] = lstm[b,t].w_l + w_t*t + bc. grid 512, block 256.
// ---------------------------------------------------------------------------
__global__ void k_a(const float* __restrict__ lstm,
                    const float* __restrict__ w_char,
                    const float* __restrict__ b_char) {
    int warp = threadIdx.x >> 5, lane = threadIdx.x & 31;
    int bt = blockIdx.x * 8 + warp;
    const float* row = lstm + (long)bt * DLN;
    float acc = 0.0f;
#pragma unroll
    for (int k = 0; k < DLN / 32; k++)
        acc = fmaf(row[lane + 32 * k], w_char[lane + 32 * k], acc);
#pragma unroll
    for (int off = 16; off; off >>= 1)
        acc += __shfl_xor_sync(0xffffffffu, acc, off);
    if (lane == 0)
        g_a[bt] = acc + w_char[DLN + CTXD] * (float)(bt & (T1 - 1)) + b_char[0];
}

// ---------------------------------------------------------------------------
// Kernel G: GRU (R11 configuration). grid (8,2), block 256
// (64 units x 4 e-quarters). One barrier/step (ping-pong h).
// f32x2 packed FMA, tanh.approx, x staged in smem.
// ---------------------------------------------------------------------------
__global__ void __launch_bounds__(256) k_gru(const int* __restrict__ char_seq,
                      const float* __restrict__ Rf, const float* __restrict__ bf,
                      const float* __restrict__ Rb, const float* __restrict__ bb) {
    extern __shared__ float x_sm[];              // [128][192]
    __shared__ float hbuf[2][EE];
    __shared__ int   s_char[T2];
    int b = blockIdx.x, dir = blockIdx.y;
    int tid = threadIdx.x;
    int i = tid >> 2, q = tid & 3;               // unit, e-quarter

    const float* R    = dir ? Rb : Rf;
    const float* bias = dir ? bb : bf;

    unsigned long long Rz2[8], Rr2[8], Rh2[8];
#pragma unroll
    for (int k = 0; k < 8; k++) {
        int e = 16 * q + 2 * k;
        Rz2[k] = packf2(R[e * G3 + i],        R[(e + 1) * G3 + i]);
        Rr2[k] = packf2(R[e * G3 + 64 + i],   R[(e + 1) * G3 + 64 + i]);
        Rh2[k] = packf2(R[e * G3 + 128 + i],  R[(e + 1) * G3 + 128 + i]);
    }
    float bz = (q == 0) ? bias[G3 + i]        : 0.0f;
    float br = (q == 0) ? bias[G3 + 64 + i]   : 0.0f;
    float bh = (q == 0) ? bias[G3 + 128 + i]  : 0.0f;

    if (tid < T2) s_char[tid] = char_seq[b * T2 + tid];
    if (tid < EE) hbuf[0][tid] = 0.0f;
    __syncthreads();

    const float* tab = g_tab + dir * VOC * G3;
    for (int idx = tid; idx < T2 * G3; idx += 256) {
        int row = idx / G3, cc = idx - row * G3;
        x_sm[idx] = tab[s_char[row] * G3 + cc];
    }
    __syncthreads();

    float h = 0.0f, y = 0.0f;
    int p = 0;
    for (int t = 0; t < T2; t++) {
        int tt = dir ? (T2 - 1 - t) : t;
        float xz = x_sm[tt * G3 + i];
        float xr = x_sm[tt * G3 + 64 + i];
        float xh = x_sm[tt * G3 + 128 + i];

        const unsigned long long* h2 =
            (const unsigned long long*)(hbuf[p] + 16 * q);
        unsigned long long az2 = packf2(bz, 0.0f);
        unsigned long long ar2 = packf2(br, 0.0f);
        unsigned long long ah2 = packf2(bh, 0.0f);
#pragma unroll
        for (int k = 0; k < 8; k++) {
            unsigned long long hv = h2[k];
            fma2(az2, hv, Rz2[k]);
            fma2(ar2, hv, Rr2[k]);
            fma2(ah2, hv, Rh2[k]);
        }
        float az = unpack_sum(az2);
        float ar = unpack_sum(ar2);
        float ah = unpack_sum(ah2);
        az += __shfl_xor_sync(0xffffffffu, az, 1);
        ar += __shfl_xor_sync(0xffffffffu, ar, 1);
        ah += __shfl_xor_sync(0xffffffffu, ah, 1);
        az += __shfl_xor_sync(0xffffffffu, az, 2);
        ar += __shfl_xor_sync(0xffffffffu, ar, 2);
        ah += __shfl_xor_sync(0xffffffffu, ah, 2);

        float z  = sigapx(xz + az);
        float r  = sigapx(xr + ar);
        float hh = tanhapx(fmaf(r, ah, xh));
        float hn = fmaf(z, h - hh, hh);          // z*h + (1-z)*hh
        if (s_char[tt] != 0) { h = hn; y = hn; }
        if (q == 0) {
            hbuf[1 - p][i] = h;
            g_ctx[(b * T2 + tt) * CTXD + dir * EE + i] = y;
        }
        p ^= 1;
        __syncthreads();
    }
}

// ---------------------------------------------------------------------------
// Kernel PQ (R11 version): per (b,s). grid 1024, block 128. 8-acc chains.
// ---------------------------------------------------------------------------
__global__ void k_pq(const float* __restrict__ conv1_w,
                     const float* __restrict__ conv2_w,
                     const float* __restrict__ conv1_b,
                     const float* __restrict__ conv2_b,
                     const float* __restrict__ w_char) {
    int bs = blockIdx.x;
    int tid = threadIdx.x;
    __shared__ float c_sm[CTXD];
    __shared__ float wsum[4];
    __shared__ float p_sm[2][EE];
    __shared__ float q01_sm[EE];

    float cv = g_ctx[bs * CTXD + tid];
    c_sm[tid] = cv;
    float pv = cv * w_char[DLN + tid];
#pragma unroll
    for (int off = 16; off; off >>= 1) pv += __shfl_xor_sync(0xffffffffu, pv, off);
    if ((tid & 31) == 0) wsum[tid >> 5] = pv;
    __syncthreads();
    if (tid == 0) g_cs[bs] = (wsum[0] + wsum[1]) + (wsum[2] + wsum[3]);

    int half = tid >> 6, o = tid & 63;
    const float* W = conv1_w + half * CTXD * EE;
    float s0 = 0.f, s1 = 0.f, s2 = 0.f, s3 = 0.f;
    float s4 = 0.f, s5 = 0.f, s6 = 0.f, s7 = 0.f;
    const float4* c4 = (const float4*)c_sm;
#pragma unroll
    for (int k = 0; k < CTXD / 4; k += 2) {
        float4 h0 = c4[k], h1 = c4[k + 1];
        int c = 4 * k;
        s0 = fmaf(h0.x, W[(c + 0) * EE + o], s0);
        s1 = fmaf(h0.y, W[(c + 1) * EE + o], s1);
        s2 = fmaf(h0.z, W[(c + 2) * EE + o], s2);
        s3 = fmaf(h0.w, W[(c + 3) * EE + o], s3);
        s4 = fmaf(h1.x, W[(c + 4) * EE + o], s4);
        s5 = fmaf(h1.y, W[(c + 5) * EE + o], s5);
        s6 = fmaf(h1.z, W[(c + 6) * EE + o], s6);
        s7 = fmaf(h1.w, W[(c + 7) * EE + o], s7);
    }
    p_sm[half][o] = ((s0 + s1) + (s2 + s3)) + ((s4 + s5) + (s6 + s7));
    __syncthreads();

    const float* W20 = conv2_w;
    const float* W21 = conv2_w + EE * EE;
    const float* P = p_sm[half];
    float qa0 = 0.f, qa1 = 0.f, qa2 = 0.f, qa3 = 0.f;
    float qb0 = 0.f, qb1 = 0.f, qb2 = 0.f, qb3 = 0.f;
#pragma unroll
    for (int k = 0; k < EE; k += 4) {
        float p0 = P[k], p1 = P[k + 1], p2 = P[k + 2], p3 = P[k + 3];
        qa0 = fmaf(p0, W20[(k + 0) * EE + o], qa0);
        qb0 = fmaf(p0, W21[(k + 0) * EE + o], qb0);
        qa1 = fmaf(p1, W20[(k + 1) * EE + o], qa1);
        qb1 = fmaf(p1, W21[(k + 1) * EE + o], qb1);
        qa2 = fmaf(p2, W20[(k + 2) * EE + o], qa2);
        qb2 = fmaf(p2, W21[(k + 2) * EE + o], qb2);
        qa3 = fmaf(p3, W20[(k + 3) * EE + o], qa3);
        qb3 = fmaf(p3, W21[(k + 3) * EE + o], qb3);
    }
    float qW20 = (qa0 + qa1) + (qa2 + qa3);   // P@W20
    float qW21 = (qb0 + qb1) + (qb2 + qb3);   // P@W21
    if (half == 0) {
        g_Q00[bs * EE + o] = qW20;
        q01_sm[o] = qW21;
    }
    __syncthreads();
    if (half == 1) {
        g_Qm [bs * EE + o] = qW20 + q01_sm[o];   // P1@W20 + P0@W21
        g_Q11[bs * EE + o] = qW21;
    }
    if (bs == 0 && half == 0) {
        float bb2 = conv2_b[o];
#pragma unroll
        for (int k = 0; k < EE; k++)
            bb2 = fmaf(conv1_b[k], W20[k * EE + o] + W21[k * EE + o], bb2);
        g_bias2[o] = bb2;
    }
}

// ---------------------------------------------------------------------------
// Kernel D: smem slope/base slab + 4-way t-register-blocked max-plus.
// grid (8 b, 16 tb), block 512. A read from g_a.
// ---------------------------------------------------------------------------
__global__ void __launch_bounds__(512) k_main(const float* __restrict__ w_char,
                                              float* __restrict__ out_final,
                                              float* __restrict__ out_cw) {
    extern __shared__ float2 sb_sm[];            // [128*64] {slope, base}
    __shared__ float A_sm[32];
    __shared__ float garr[T2];
    int b = blockIdx.x, t0 = blockIdx.y * 32;
    int tid = threadIdx.x;

    float wi = w_char[DLN + CTXD + 1];
    if (tid < T2) garr[tid] = g_cs[b * T2 + tid] + wi * (float)tid;
    if (tid >= T2 && tid < T2 + 32)
        A_sm[tid - T2] = g_a[b * T1 + t0 + (tid - T2)];
    __syncthreads();

    {
        float* cwb = out_cw + ((long)(b * T1 + t0)) * T2;
#pragma unroll
        for (int it = 0; it < 8; it++) {
            int idx = tid + it * 512;
            int tl = idx >> 7, s = idx & (T2 - 1);
            cwb[tl * T2 + s] = A_sm[tl] + garr[s];
        }
    }

    {
        int ocol = tid & 63;
        float b2 = g_bias2[ocol];
        const float* Qb  = g_Q00 + b * T2 * EE;
        const float* Qmb = g_Qm  + b * T2 * EE;
        const float* Q1b = g_Q11 + b * T2 * EE;
#pragma unroll
        for (int it = 0; it < 16; it++) {
            int idx = tid + it * 512;
            int s = idx >> 6;
            float slope = 0.0f, base = -INFINITY;
            if (s < NS) {
                float q0 = Qb [idx];
                float qm = Qmb[idx + EE];
                float q1 = Q1b[idx + 2 * EE];
                slope = (q0 + qm) + q1;
                base  = fmaf(garr[s], q0,
                        fmaf(garr[s + 1], qm,
                        fmaf(garr[s + 2], q1, b2)));
            }
            sb_sm[idx] = make_float2(slope, base);
        }
    }
    __syncthreads();

    {
        int tg = tid >> 6, o = tid & 63;
        float A0 = A_sm[tg + 0],  A1 = A_sm[tg + 8];
        float A2 = A_sm[tg + 16], A3 = A_sm[tg + 24];
        float m0 = -INFINITY, m1 = -INFINITY, m2 = -INFINITY, m3 = -INFINITY;
        const float2* sb = sb_sm + o;
#pragma unroll 8
        for (int s = 0; s < SLAB; s++) {
            float2 v = sb[s * EE];
            m0 = fmaxf(m0, fmaf(A0, v.x, v.y));
            m1 = fmaxf(m1, fmaf(A1, v.x, v.y));
            m2 = fmaxf(m2, fmaf(A2, v.x, v.y));
            m3 = fmaxf(m3, fmaf(A3, v.x, v.y));
        }
        long ob = (long)(b * T1 + t0) * EE + o;
        out_final[ob + (tg + 0)  * EE] = m0;
        out_final[ob + (tg + 8)  * EE] = m1;
        out_final[ob + (tg + 16) * EE] = m2;
        out_final[ob + (tg + 24) * EE] = m3;
    }
}

// ---------------------------------------------------------------------------
extern "C" void kernel_launch(void* const* d_in, const int* in_sizes, int n_in,
                              void* d_out, int out_size) {
    const float* lstm     = (const float*)d_in[0];
    const int*   char_seq = (const int*)  d_in[1];
    const float* emb      = (const float*)d_in[2];
    const float* Kf       = (const float*)d_in[3];
    const float* Rf       = (const float*)d_in[4];
    const float* bf       = (const float*)d_in[5];
    const float* Kb       = (const float*)d_in[6];
    const float* Rb       = (const float*)d_in[7];
    const float* bb       = (const float*)d_in[8];
    const float* w_char   = (const float*)d_in[9];
    const float* b_char   = (const float*)d_in[10];
    const float* conv1_w  = (const float*)d_in[11];
    const float* conv1_b  = (const float*)d_in[12];
    const float* conv2_w  = (const float*)d_in[13];
    const float* conv2_b  = (const float*)d_in[14];

    float* out_final = (float*)d_out;                 // (8,512,64)
    float* out_cw    = out_final + NB * T1 * EE;      // (8,512,128,1)

    (void)cudaFuncSetAttribute(k_gru, cudaFuncAttributeMaxDynamicSharedMemorySize,
                               T2 * G3 * (int)sizeof(float));
    (void)cudaFuncSetAttribute(k_main, cudaFuncAttributeMaxDynamicSharedMemorySize,
                               SLAB * EE * (int)sizeof(float2));

    // Launch order places k_gru at index 3 (the ncu capture slot).
    k_tab<<<VOC, G3>>>(0, emb, Kf, bf);                                  // 0
    k_tab<<<VOC, G3>>>(1, emb, Kb, bb);                                  // 1
    k_a<<<NB * T1 / 8, 256>>>(lstm, w_char, b_char);                     // 2
    k_gru<<<dim3(NB, 2), 256, T2 * G3 * sizeof(float)>>>(char_seq,       // 3
                                                         Rf, bf, Rb, bb);
    k_pq<<<NB * T2, CTXD>>>(conv1_w, conv2_w, conv1_b, conv2_b, w_char); // 4
    k_main<<<dim3(NB, 16), 512, SLAB * EE * sizeof(float2)>>>(w_char,    // 5
                                                              out_final, out_cw);
}

// round 17
// speedup vs baseline: 1.2445x; 1.1805x over previous
#include <cuda_runtime.h>
#include <math.h>

// Problem constants
#define NB   8
#define T1   512
#define T2   128
#define EE   64      // E
#define G3   192     // 3*E
#define DLN  256
#define CTXD 128     // 2*E
#define VOC  129     // LA+1
#define NS   126     // T2-2 valid conv output positions
#define SLAB 128     // padded slab rows (power of 2)

// Scratch (device globals)
__device__ float g_tab[2 * VOC * G3];        // per-dir input-gate table
__device__ float g_ctx[NB * T2 * CTXD];      // [b][s][fwd|bwd]
__device__ float g_Q00[NB * T2 * EE];
__device__ float g_Qm [NB * T2 * EE];
__device__ float g_Q11[NB * T2 * EE];
__device__ float g_cs[NB * T2];              // ctx . w_c
__device__ float g_a [NB * T1];              // A = lstm.w_l + w_t*t + bc
__device__ float g_bias2[EE];

__device__ __forceinline__ float tanhapx(float v) {
    float r;
    asm("tanh.approx.f32 %0, %1;" : "=f"(r) : "f"(v));
    return r;
}
__device__ __forceinline__ float sigapx(float v) {
    return fmaf(0.5f, tanhapx(0.5f * v), 0.5f);
}
__device__ __forceinline__ unsigned long long packf2(float lo, float hi) {
    unsigned long long r;
    asm("mov.b64 %0, {%1, %2};" : "=l"(r) : "f"(lo), "f"(hi));
    return r;
}
__device__ __forceinline__ void fma2(unsigned long long& acc,
                                     unsigned long long a, unsigned long long b) {
    asm("fma.rn.f32x2 %0, %1, %2, %0;" : "+l"(acc) : "l"(a), "l"(b));
}
__device__ __forceinline__ float unpack_sum(unsigned long long v) {
    float lo, hi;
    asm("mov.b64 {%0, %1}, %2;" : "=f"(lo), "=f"(hi) : "l"(v));
    return lo + hi;
}

// ---------------------------------------------------------------------------
// Kernel T: input-gate table for ONE direction. grid 129, block 192.
// ---------------------------------------------------------------------------
__global__ void k_tab(int dir,
                      const float* __restrict__ emb_table,
                      const float* __restrict__ K, const float* __restrict__ bias) {
    int c = blockIdx.x;
    int u = threadIdx.x;
    __shared__ float e_sm[EE];
    if (u < EE) e_sm[u] = emb_table[c * EE + u];
    __syncthreads();
    float a0 = bias[u], a1 = 0.f, a2 = 0.f, a3 = 0.f;
    const float4* e4 = (const float4*)e_sm;
#pragma unroll
    for (int k = 0; k < 16; k++) {
        float4 hv = e4[k];
        int e = 4 * k;
        a0 = fmaf(hv.x, K[(e + 0) * G3 + u], a0);
        a1 = fmaf(hv.y, K[(e + 1) * G3 + u], a1);
        a2 = fmaf(hv.z, K[(e + 2) * G3 + u], a2);
        a3 = fmaf(hv.w, K[(e + 3) * G3 + u], a3);
    }
    g_tab[(dir * VOC + c) * G3 + u] = (a0 + a1) + (a2 + a3);
}

// ---------------------------------------------------------------------------
// Kernel A: g_a[b,t] = lstm[b,t].w_l + w_t*t + bc. grid 512, block 256.
// ---------------------------------------------------------------------------
__global__ void k_a(const float* __restrict__ lstm,
                    const float* __restrict__ w_char,
                    const float* __restrict__ b_char) {
    int warp = threadIdx.x >> 5, lane = threadIdx.x & 31;
    int bt = blockIdx.x * 8 + warp;
    const float* row = lstm + (long)bt * DLN;
    float acc = 0.0f;
#pragma unroll
    for (int k = 0; k < DLN / 32; k++)
        acc = fmaf(row[lane + 32 * k], w_char[lane + 32 * k], acc);
#pragma unroll
    for (int off = 16; off; off >>= 1)
        acc += __shfl_xor_sync(0xffffffffu, acc, off);
    if (lane == 0)
        g_a[bt] = acc + w_char[DLN + CTXD] * (float)(bt & (T1 - 1)) + b_char[0];
}

// ---------------------------------------------------------------------------
// Kernel G v3: GRU. grid (8,2), block 128 (64 units x 2 e-halves).
// ONE shfl round per gate, 2x8 split FFMA2 chains, 4-warp barrier,
// ping-pong h, tanh.approx activations, x staged in smem.
// ---------------------------------------------------------------------------
__global__ void __launch_bounds__(128) k_gru(const int* __restrict__ char_seq,
                      const float* __restrict__ Rf, const float* __restrict__ bf,
                      const float* __restrict__ Rb, const float* __restrict__ bb) {
    extern __shared__ float x_sm[];              // [128][192]
    __shared__ float hbuf[2][EE];
    __shared__ int   s_char[T2];
    int b = blockIdx.x, dir = blockIdx.y;
    int tid = threadIdx.x;
    int i = tid >> 1, half = tid & 1;            // unit, e-half (32 e each)

    const float* R    = dir ? Rb : Rf;
    const float* bias = dir ? bb : bf;

    // Pack R column slices: e in [32*half, 32*half+32) as 16 f32x2 per gate.
    unsigned long long Rz2[16], Rr2[16], Rh2[16];
#pragma unroll
    for (int k = 0; k < 16; k++) {
        int e = 32 * half + 2 * k;
        Rz2[k] = packf2(R[e * G3 + i],        R[(e + 1) * G3 + i]);
        Rr2[k] = packf2(R[e * G3 + 64 + i],   R[(e + 1) * G3 + 64 + i]);
        Rh2[k] = packf2(R[e * G3 + 128 + i],  R[(e + 1) * G3 + 128 + i]);
    }
    float bz = (half == 0) ? bias[G3 + i]        : 0.0f;
    float br = (half == 0) ? bias[G3 + 64 + i]   : 0.0f;
    float bh = (half == 0) ? bias[G3 + 128 + i]  : 0.0f;

    s_char[tid] = char_seq[b * T2 + tid];        // 128 threads == T2
    if (tid < EE) hbuf[0][tid] = 0.0f;
    __syncthreads();

    // Stage x: warp w handles rows [32w, 32w+32); 48 float4 per row.
    {
        int w = tid >> 5, lane = tid & 31;
        const float* tab = g_tab + dir * VOC * G3;
#pragma unroll 4
        for (int rr = 0; rr < 32; rr++) {
            int row = w * 32 + rr;
            const float4* src = (const float4*)(tab + s_char[row] * G3);
            float4* dst = (float4*)(x_sm + row * G3);
            dst[lane] = src[lane];
            if (lane < 16) dst[lane + 32] = src[lane + 32];
        }
    }
    __syncthreads();

    float h = 0.0f, y = 0.0f;
    int p = 0;
    for (int t = 0; t < T2; t++) {
        int tt = dir ? (T2 - 1 - t) : t;
        float xz = x_sm[tt * G3 + i];
        float xr = x_sm[tt * G3 + 64 + i];
        float xh = x_sm[tt * G3 + 128 + i];

        const unsigned long long* h2 =
            (const unsigned long long*)(hbuf[p] + 32 * half);
        unsigned long long az0 = packf2(bz, 0.0f), az1 = packf2(0.0f, 0.0f);
        unsigned long long ar0 = packf2(br, 0.0f), ar1 = packf2(0.0f, 0.0f);
        unsigned long long ah0 = packf2(bh, 0.0f), ah1 = packf2(0.0f, 0.0f);
#pragma unroll
        for (int k = 0; k < 8; k++) {
            unsigned long long hv = h2[k];
            fma2(az0, hv, Rz2[k]);
            fma2(ar0, hv, Rr2[k]);
            fma2(ah0, hv, Rh2[k]);
        }
#pragma unroll
        for (int k = 8; k < 16; k++) {
            unsigned long long hv = h2[k];
            fma2(az1, hv, Rz2[k]);
            fma2(ar1, hv, Rr2[k]);
            fma2(ah1, hv, Rh2[k]);
        }
        float az = unpack_sum(az0) + unpack_sum(az1);
        float ar = unpack_sum(ar0) + unpack_sum(ar1);
        float ah = unpack_sum(ah0) + unpack_sum(ah1);
        // single reduce round: partner lane (xor 1) holds the other e-half
        az += __shfl_xor_sync(0xffffffffu, az, 1);
        ar += __shfl_xor_sync(0xffffffffu, ar, 1);
        ah += __shfl_xor_sync(0xffffffffu, ah, 1);

        float z  = sigapx(xz + az);
        float r  = sigapx(xr + ar);
        float hh = tanhapx(fmaf(r, ah, xh));
        float hn = fmaf(z, h - hh, hh);          // z*h + (1-z)*hh
        if (s_char[tt] != 0) { h = hn; y = hn; }
        if (half == 0) {
            hbuf[1 - p][i] = h;
            g_ctx[(b * T2 + tt) * CTXD + dir * EE + i] = y;
        }
        p ^= 1;
        __syncthreads();
    }
}

// ---------------------------------------------------------------------------
// Kernel PQ (R11 version): per (b,s). grid 1024, block 128. 8-acc chains.
// ---------------------------------------------------------------------------
__global__ void k_pq(const float* __restrict__ conv1_w,
                     const float* __restrict__ conv2_w,
                     const float* __restrict__ conv1_b,
                     const float* __restrict__ conv2_b,
                     const float* __restrict__ w_char) {
    int bs = blockIdx.x;
    int tid = threadIdx.x;
    __shared__ float c_sm[CTXD];
    __shared__ float wsum[4];
    __shared__ float p_sm[2][EE];
    __shared__ float q01_sm[EE];

    float cv = g_ctx[bs * CTXD + tid];
    c_sm[tid] = cv;
    float pv = cv * w_char[DLN + tid];
#pragma unroll
    for (int off = 16; off; off >>= 1) pv += __shfl_xor_sync(0xffffffffu, pv, off);
    if ((tid & 31) == 0) wsum[tid >> 5] = pv;
    __syncthreads();
    if (tid == 0) g_cs[bs] = (wsum[0] + wsum[1]) + (wsum[2] + wsum[3]);

    int half = tid >> 6, o = tid & 63;
    const float* W = conv1_w + half * CTXD * EE;
    float s0 = 0.f, s1 = 0.f, s2 = 0.f, s3 = 0.f;
    float s4 = 0.f, s5 = 0.f, s6 = 0.f, s7 = 0.f;
    const float4* c4 = (const float4*)c_sm;
#pragma unroll
    for (int k = 0; k < CTXD / 4; k += 2) {
        float4 h0 = c4[k], h1 = c4[k + 1];
        int c = 4 * k;
        s0 = fmaf(h0.x, W[(c + 0) * EE + o], s0);
        s1 = fmaf(h0.y, W[(c + 1) * EE + o], s1);
        s2 = fmaf(h0.z, W[(c + 2) * EE + o], s2);
        s3 = fmaf(h0.w, W[(c + 3) * EE + o], s3);
        s4 = fmaf(h1.x, W[(c + 4) * EE + o], s4);
        s5 = fmaf(h1.y, W[(c + 5) * EE + o], s5);
        s6 = fmaf(h1.z, W[(c + 6) * EE + o], s6);
        s7 = fmaf(h1.w, W[(c + 7) * EE + o], s7);
    }
    p_sm[half][o] = ((s0 + s1) + (s2 + s3)) + ((s4 + s5) + (s6 + s7));
    __syncthreads();

    const float* W20 = conv2_w;
    const float* W21 = conv2_w + EE * EE;
    const float* P = p_sm[half];
    float qa0 = 0.f, qa1 = 0.f, qa2 = 0.f, qa3 = 0.f;
    float qb0 = 0.f, qb1 = 0.f, qb2 = 0.f, qb3 = 0.f;
#pragma unroll
    for (int k = 0; k < EE; k += 4) {
        float p0 = P[k], p1 = P[k + 1], p2 = P[k + 2], p3 = P[k + 3];
        qa0 = fmaf(p0, W20[(k + 0) * EE + o], qa0);
        qb0 = fmaf(p0, W21[(k + 0) * EE + o], qb0);
        qa1 = fmaf(p1, W20[(k + 1) * EE + o], qa1);
        qb1 = fmaf(p1, W21[(k + 1) * EE + o], qb1);
        qa2 = fmaf(p2, W20[(k + 2) * EE + o], qa2);
        qb2 = fmaf(p2, W21[(k + 2) * EE + o], qb2);
        qa3 = fmaf(p3, W20[(k + 3) * EE + o], qa3);
        qb3 = fmaf(p3, W21[(k + 3) * EE + o], qb3);
    }
    float qW20 = (qa0 + qa1) + (qa2 + qa3);   // P@W20
    float qW21 = (qb0 + qb1) + (qb2 + qb3);   // P@W21
    if (half == 0) {
        g_Q00[bs * EE + o] = qW20;
        q01_sm[o] = qW21;
    }
    __syncthreads();
    if (half == 1) {
        g_Qm [bs * EE + o] = qW20 + q01_sm[o];   // P1@W20 + P0@W21
        g_Q11[bs * EE + o] = qW21;
    }
    if (bs == 0 && half == 0) {
        float bb2 = conv2_b[o];
#pragma unroll
        for (int k = 0; k < EE; k++)
            bb2 = fmaf(conv1_b[k], W20[k * EE + o] + W21[k * EE + o], bb2);
        g_bias2[o] = bb2;
    }
}

// ---------------------------------------------------------------------------
// Kernel D: smem slope/base slab + 4-way t-register-blocked max-plus.
// grid (8 b, 16 tb), block 512. A read from g_a.
// ---------------------------------------------------------------------------
__global__ void __launch_bounds__(512) k_main(const float* __restrict__ w_char,
                                              float* __restrict__ out_final,
                                              float* __restrict__ out_cw) {
    extern __shared__ float2 sb_sm[];            // [128*64] {slope, base}
    __shared__ float A_sm[32];
    __shared__ float garr[T2];
    int b = blockIdx.x, t0 = blockIdx.y * 32;
    int tid = threadIdx.x;

    float wi = w_char[DLN + CTXD + 1];
    if (tid < T2) garr[tid] = g_cs[b * T2 + tid] + wi * (float)tid;
    if (tid >= T2 && tid < T2 + 32)
        A_sm[tid - T2] = g_a[b * T1 + t0 + (tid - T2)];
    __syncthreads();

    {
        float* cwb = out_cw + ((long)(b * T1 + t0)) * T2;
#pragma unroll
        for (int it = 0; it < 8; it++) {
            int idx = tid + it * 512;
            int tl = idx >> 7, s = idx & (T2 - 1);
            cwb[tl * T2 + s] = A_sm[tl] + garr[s];
        }
    }

    {
        int ocol = tid & 63;
        float b2 = g_bias2[ocol];
        const float* Qb  = g_Q00 + b * T2 * EE;
        const float* Qmb = g_Qm  + b * T2 * EE;
        const float* Q1b = g_Q11 + b * T2 * EE;
#pragma unroll
        for (int it = 0; it < 16; it++) {
            int idx = tid + it * 512;
            int s = idx >> 6;
            float slope = 0.0f, base = -INFINITY;
            if (s < NS) {
                float q0 = Qb [idx];
                float qm = Qmb[idx + EE];
                float q1 = Q1b[idx + 2 * EE];
                slope = (q0 + qm) + q1;
                base  = fmaf(garr[s], q0,
                        fmaf(garr[s + 1], qm,
                        fmaf(garr[s + 2], q1, b2)));
            }
            sb_sm[idx] = make_float2(slope, base);
        }
    }
    __syncthreads();

    {
        int tg = tid >> 6, o = tid & 63;
        float A0 = A_sm[tg + 0],  A1 = A_sm[tg + 8];
        float A2 = A_sm[tg + 16], A3 = A_sm[tg + 24];
        float m0 = -INFINITY, m1 = -INFINITY, m2 = -INFINITY, m3 = -INFINITY;
        const float2* sb = sb_sm + o;
#pragma unroll 8
        for (int s = 0; s < SLAB; s++) {
            float2 v = sb[s * EE];
            m0 = fmaxf(m0, fmaf(A0, v.x, v.y));
            m1 = fmaxf(m1, fmaf(A1, v.x, v.y));
            m2 = fmaxf(m2, fmaf(A2, v.x, v.y));
            m3 = fmaxf(m3, fmaf(A3, v.x, v.y));
        }
        long ob = (long)(b * T1 + t0) * EE + o;
        out_final[ob + (tg + 0)  * EE] = m0;
        out_final[ob + (tg + 8)  * EE] = m1;
        out_final[ob + (tg + 16) * EE] = m2;
        out_final[ob + (tg + 24) * EE] = m3;
    }
}

// ---------------------------------------------------------------------------
extern "C" void kernel_launch(void* const* d_in, const int* in_sizes, int n_in,
                              void* d_out, int out_size) {
    const float* lstm     = (const float*)d_in[0];
    const int*   char_seq = (const int*)  d_in[1];
    const float* emb      = (const float*)d_in[2];
    const float* Kf       = (const float*)d_in[3];
    const float* Rf       = (const float*)d_in[4];
    const float* bf       = (const float*)d_in[5];
    const float* Kb       = (const float*)d_in[6];
    const float* Rb       = (const float*)d_in[7];
    const float* bb       = (const float*)d_in[8];
    const float* w_char   = (const float*)d_in[9];
    const float* b_char   = (const float*)d_in[10];
    const float* conv1_w  = (const float*)d_in[11];
    const float* conv1_b  = (const float*)d_in[12];
    const float* conv2_w  = (const float*)d_in[13];
    const float* conv2_b  = (const float*)d_in[14];

    float* out_final = (float*)d_out;                 // (8,512,64)
    float* out_cw    = out_final + NB * T1 * EE;      // (8,512,128,1)

    (void)cudaFuncSetAttribute(k_gru, cudaFuncAttributeMaxDynamicSharedMemorySize,
                               T2 * G3 * (int)sizeof(float));
    (void)cudaFuncSetAttribute(k_main, cudaFuncAttributeMaxDynamicSharedMemorySize,
                               SLAB * EE * (int)sizeof(float2));

    // Launch order places k_gru at index 3 (the ncu capture slot).
    k_tab<<<VOC, G3>>>(0, emb, Kf, bf);                                  // 0
    k_tab<<<VOC, G3>>>(1, emb, Kb, bb);                                  // 1
    k_a<<<NB * T1 / 8, 256>>>(lstm, w_char, b_char);                     // 2
    k_gru<<<dim3(NB, 2), 128, T2 * G3 * sizeof(float)>>>(char_seq,       // 3
                                                         Rf, bf, Rb, bb);
    k_pq<<<NB * T2, CTXD>>>(conv1_w, conv2_w, conv1_b, conv2_b, w_char); // 4
    k_main<<<dim3(NB, 16), 512, SLAB * EE * sizeof(float2)>>>(w_char,    // 5
                                                              out_final, out_cw);
}